// round 15
// baseline (speedup 1.0000x reference)
#include <cuda_runtime.h>

// ReduceBoundingBoxes: decode + threshold + stable sort + greedy NMS.
// SINGLE BLOCK (1024 threads), zero grid barriers, zero persistent-state
// resets. Phases separated by __syncthreads only:
//   P0: zero output; decode cells (float4), write per-cell box table,
//       compact packed u64 keys into SMEM via block-local atomic
//   P1: bitonic sort of keys, descending (unique keys -> stable order)
//   P2: extract sorted boxes/scores to global; act ballot bitmap + prefix;
//       compact active boxes/ranks directly into SMEM
//   P3: warp-ballot suppression bit-matrix over actives (division-free IoU)
//   P4: sparse chunked greedy scan + map back + scatter
//
// key = (score_bits << 32) | (0xFFFFFFFF - cell): scores are positive floats
// so bit pattern is order-isomorphic; descending key order == score desc,
// cell asc (the reference's stable argsort). Keys unique. Zero padding sorts
// last (real keys have score bits ~0x3F66... > 0).

#define NCELL   9216
#define PDIM    96
#define WIDTHF  3072.0f
#define HEIGHTF 2304.0f
#define XPSF    32.0f    // multiplies ROW index (P dim)
#define YPSF    24.0f    // multiplies COL index (Q dim)
#define MAXNW   144      // ceil(9216/64)
#define NTHR    1024
#define DSMEM_BYTES 184320

typedef unsigned long long u64;

// -------- global scratch (static device memory) ----------------------------
__device__ float4 g_cellbox[NCELL];   // decoded box per valid cell
__device__ float  g_sscore[NCELL];    // sorted scores
__device__ float4 g_sbox[NCELL];      // sorted boxes
__device__ u64    g_sup[(size_t)NCELL * MAXNW];   // matrix fallback (A large)

extern __shared__ unsigned char dyn_smem[];

__global__ __launch_bounds__(NTHR, 1)
void rbb_single(const float* __restrict__ x, float* __restrict__ out)
{
    const int tid  = threadIdx.x;
    const int wid  = tid >> 5;
    const int lane = tid & 31;

    __shared__ int s_cnt;
    __shared__ unsigned s_bm[289];     // act bitmap (32-bit granules)
    __shared__ int      s_pfx[290];    // exclusive prefix popcounts
    __shared__ u64 skeepA[MAXNW];
    __shared__ u64 skeepR[MAXNW];
    __shared__ u64 snz[MAXNW];

    u64* skey = (u64*)dyn_smem;        // [Mp] during P0-P2; dead after

    if (tid == 0) s_cnt = 0;

    // ---------------- P0: zero output + decode + key compaction --------------
    {
        float4* o4 = (float4*)out;     // 46080 floats = 11520 float4
        for (int i = tid; i < 11520; i += NTHR)
            o4[i] = make_float4(0.f, 0.f, 0.f, 0.f);
    }
    __syncthreads();

    {
        const float4* x4 = (const float4*)x;   // planes of 2304 float4 each
        for (int i = tid; i < NCELL / 4; i += NTHR) {
            float4 s4 = x4[i];
            int c0 = i << 2;
            bool v0 = s4.x > 0.9f, v1 = s4.y > 0.9f;
            bool v2 = s4.z > 0.9f, v3 = s4.w > 0.9f;
            int cnt = (int)v0 + (int)v1 + (int)v2 + (int)v3;
            if (cnt) {
                float4 a4 = x4[2304 + i];      // x[1]
                float4 b4 = x4[4608 + i];      // x[2]
                float4 c4 = x4[6912 + i];      // x[3]
                float4 d4 = x4[9216 + i];      // x[4]
                int p  = c0 / PDIM;
                int q0 = c0 - p * PDIM;        // groups never cross rows (96%4==0)
                float ii = (float)p * XPSF;
                int base = atomicAdd(&s_cnt, cnt);

                float sv[4]  = { s4.x, s4.y, s4.z, s4.w };
                float av[4]  = { a4.x, a4.y, a4.z, a4.w };
                float bv[4]  = { b4.x, b4.y, b4.z, b4.w };
                float cv[4]  = { c4.x, c4.y, c4.z, c4.w };
                float dv[4]  = { d4.x, d4.y, d4.z, d4.w };
                bool  vv[4]  = { v0, v1, v2, v3 };
                #pragma unroll
                for (int j = 0; j < 4; j++) {
                    if (vv[j]) {
                        int   c  = c0 + j;
                        float jj = (float)(q0 + j) * YPSF;
                        float bx1 = av[j] * WIDTHF  + ii;
                        float by1 = bv[j] * HEIGHTF + jj;
                        float bx2 = (cv[j] - av[j]) * WIDTHF  + ii;
                        float by2 = (dv[j] - bv[j]) * HEIGHTF + jj;
                        g_cellbox[c] = make_float4(bx1, by1, bx2, by2);
                        skey[base++] = ((u64)__float_as_uint(sv[j]) << 32)
                                     | (u64)(0xFFFFFFFFu - (unsigned)c);
                    }
                }
            }
        }
    }
    __syncthreads();

    const int M = s_cnt;
    if (M == 0) return;                 // output already zeroed

    // pad to power of two (>= 1024 keeps every thread busy cheaply)
    int Mp = 1024;
    while (Mp < M) Mp <<= 1;
    for (int i = M + tid; i < Mp; i += NTHR) skey[i] = 0ull;

    // ---------------- P1: bitonic sort, descending ---------------------------
    for (int k = 2; k <= Mp; k <<= 1) {
        for (int j = k >> 1; j > 0; j >>= 1) {
            __syncthreads();
            for (int i = tid; i < Mp; i += NTHR) {
                int ixj = i ^ j;
                if (ixj > i) {
                    u64 a = skey[i], b = skey[ixj];
                    bool desc = ((i & k) == 0);
                    if (desc ? (a < b) : (a > b)) {
                        skey[i]   = b;
                        skey[ixj] = a;
                    }
                }
            }
        }
    }
    __syncthreads();

    // ---------------- P2: extract + act bitmap + active compaction -----------
    const int n32 = (M + 31) >> 5;
    {
        // extract sorted boxes/scores; ballot act flags (warp-uniform loops)
        const int M32 = n32 << 5;
        for (int t = 0; t < M32; t += NTHR) {
            int r = t + tid;
            bool act = false;
            if (r < M) {
                u64 key = skey[r];
                int c = (int)(0xFFFFFFFFu - (unsigned)key);
                float4 b = g_cellbox[c];
                g_sbox[r]   = b;
                g_sscore[r] = __uint_as_float((unsigned)(key >> 32));
                act = (b.z > b.x) && (b.w > b.y);
            }
            unsigned bal = __ballot_sync(0xFFFFFFFFu, act);
            if (lane == 0 && (t + tid) < M32 + 32) {
                int w = (t + tid) >> 5;
                if (w < n32) s_bm[w] = bal;
            }
        }
        __syncthreads();
        if (tid == 0) {
            int acc = 0;
            for (int i = 0; i < n32; i++) { s_pfx[i] = acc; acc += __popc(s_bm[i]); }
            s_pfx[n32] = acc;
        }
        __syncthreads();
    }
    const int A  = s_pfx[n32];
    const int na = (A + 63) >> 6;

    // SMEM overlay (skey dead): sabox [0,16A) | samap [16A,20A) | ssup after
    float4* sabox = (float4*)dyn_smem;
    int*    samap = (int*)(dyn_smem + (size_t)A * 16);
    size_t  supoff = ((size_t)A * 20 + 7) & ~(size_t)7;
    u64*    ssup  = (u64*)(dyn_smem + supoff);
    const bool fast = (supoff + (size_t)A * na * 8) <= DSMEM_BYTES;

    // compact actives (reads s_bm/g_sbox, writes the overlay - skey not read)
    __syncthreads();
    for (int r = tid; r < M; r += NTHR) {
        unsigned w = s_bm[r >> 5];
        if ((w >> (r & 31)) & 1u) {
            int pos = s_pfx[r >> 5] + __popc(w & ((1u << (r & 31)) - 1u));
            sabox[pos] = g_sbox[r];
            samap[pos] = r;
        }
    }
    if (tid < MAXNW) {
        snz[tid] = 0ull;
        if (tid < na) {
            int nb = A - (tid << 6);
            skeepA[tid] = (nb >= 64) ? ~0ull : ((1ull << nb) - 1ull);
        }
        int nwR = (M + 63) >> 6;
        if (tid < nwR) {
            int nb = M - (tid << 6);
            skeepR[tid] = (nb >= 64) ? ~0ull : ((1ull << nb) - 1ull);
        }
    }
    __syncthreads();

    // ---------------- P3: ballot suppression bit-matrix ----------------------
    // Division-free: denom > 0, so inter/denom > 0.5 <=> inter > 0.5*denom.
    for (int i = wid; i < A; i += 32) {
        float4 bi = sabox[i];
        float  ai = (bi.z - bi.x) * (bi.w - bi.y);
        u64 rowor = 0;
        for (int w = (i >> 6); w < na; w++) {
            int j1 = (w << 6) + lane;
            int j2 = j1 + 32;
            bool p1 = false, p2 = false;
            if (j1 > i && j1 < A) {
                float4 bj = sabox[j1];
                float  aj = (bj.z - bj.x) * (bj.w - bj.y);
                float iw = fmaxf(fminf(bi.z, bj.z) - fmaxf(bi.x, bj.x), 0.0f);
                float ih = fmaxf(fminf(bi.w, bj.w) - fmaxf(bi.y, bj.y), 0.0f);
                float inter = iw * ih;
                p1 = inter > 0.5f * (ai + aj - inter + 1e-9f);
            }
            if (j2 > i && j2 < A) {
                float4 bj = sabox[j2];
                float  aj = (bj.z - bj.x) * (bj.w - bj.y);
                float iw = fmaxf(fminf(bi.z, bj.z) - fmaxf(bi.x, bj.x), 0.0f);
                float ih = fmaxf(fminf(bi.w, bj.w) - fmaxf(bi.y, bj.y), 0.0f);
                float inter = iw * ih;
                p2 = inter > 0.5f * (ai + aj - inter + 1e-9f);
            }
            unsigned lo = __ballot_sync(0xFFFFFFFFu, p1);
            unsigned hi = __ballot_sync(0xFFFFFFFFu, p2);
            u64 bits = (u64)lo | ((u64)hi << 32);
            if (lane == 0) {
                if (fast) ssup[(size_t)i * na + w] = bits;
                else      g_sup[(size_t)i * na + w] = bits;
            }
            rowor |= bits;
        }
        if (lane == 0 && rowor)
            atomicOr(&snz[i >> 6], 1ull << (i & 63));
    }
    __syncthreads();

    // ---------------- P4: sparse chunked greedy scan -------------------------
    if (tid < 32 && A > 0) {
        const int ln = tid;
        for (int c = 0; c < na; c++) {
            const int base = c << 6;

            if (ln == 0) {
                u64 kw  = skeepA[c];
                u64 rem = kw & snz[c];
                while (rem) {
                    int b = __ffsll((long long)rem) - 1;
                    u64 s = fast ? ssup[(size_t)(base + b) * na + c]
                                 : g_sup[(size_t)(base + b) * na + c];
                    kw  &= ~s;          // bits in s are strictly > b
                    rem &= ~s;
                    rem &= rem - 1;     // clear processed (lowest) bit
                }
                skeepA[c] = kw;
            }
            __syncwarp();

            const u64 kwnz = skeepA[c] & snz[c];
            if (kwnz) {
                for (int w = c + 1 + ln; w < na; w += 32) {
                    u64 acc = 0, t = kwnz;
                    while (t) {
                        int b = __ffsll((long long)t) - 1;
                        t &= t - 1;
                        acc |= fast ? ssup[(size_t)(base + b) * na + w]
                                    : g_sup[(size_t)(base + b) * na + w];
                    }
                    skeepA[w] &= ~acc;
                }
            }
            __syncwarp();
        }
    }
    __syncthreads();

    // map suppressed actives back to global sorted ranks
    for (int a = tid; a < A; a += NTHR) {
        if (!((skeepA[a >> 6] >> (a & 63)) & 1ull)) {
            int r = samap[a];
            atomicAnd(&skeepR[r >> 6], ~(1ull << (r & 63)));
        }
    }
    __syncthreads();

    // scatter kept rows (output zeroed in P0)
    for (int r = tid; r < M; r += NTHR) {
        if ((skeepR[r >> 6] >> (r & 63)) & 1ull) {
            float4 b = g_sbox[r];
            out[r * 5 + 0] = g_sscore[r];
            out[r * 5 + 1] = b.x;
            out[r * 5 + 2] = b.y;
            out[r * 5 + 3] = b.z - b.x;
            out[r * 5 + 4] = b.w - b.y;
        }
    }
}

// ---------------------------------------------------------------------------
extern "C" void kernel_launch(void* const* d_in, const int* in_sizes, int n_in,
                              void* d_out, int out_size)
{
    (void)in_sizes; (void)n_in; (void)out_size;
    const float* x   = (const float*)d_in[0];
    float*       out = (float*)d_out;

    cudaFuncSetAttribute(rbb_single,
                         cudaFuncAttributeMaxDynamicSharedMemorySize,
                         DSMEM_BYTES);

    rbb_single<<<1, NTHR, DSMEM_BYTES>>>(x, out);
}